// round 2
// baseline (speedup 1.0000x reference)
#include <cuda_runtime.h>
#include <math.h>

#define NL 4
#define NB 32
#define NH 512
#define NV 32000
#define NT 51

typedef unsigned long long u64;

// -------- persistent device scratch (zero-initialized at module load) --------
__device__ float g_h[2][NL][NB][NH];     // ping-pong hidden state (clamped)
__device__ float g_c[NL][NB][NH];        // cell state (clamped), elementwise per block -> no ping-pong
__device__ float g_xbuf[2][NB][NH];      // inter-layer activations (unclamped h)
__device__ float g_htop[1664 * NH];      // top-layer hidden per step, padded 1632 -> 1664 rows

// -------- packed f32x2 helpers (sm_103a FFMA2 path) --------
__device__ __forceinline__ u64 pk2(float lo, float hi) {
    u64 r;
    asm("mov.b64 %0, {%1, %2};" : "=l"(r) : "r"(__float_as_uint(lo)), "r"(__float_as_uint(hi)));
    return r;
}
__device__ __forceinline__ void upk2(u64 v, float &lo, float &hi) {
    unsigned a, b;
    asm("mov.b64 {%0, %1}, %2;" : "=r"(a), "=r"(b) : "l"(v));
    lo = __uint_as_float(a); hi = __uint_as_float(b);
}
__device__ __forceinline__ u64 ffma2(u64 a, u64 b, u64 c) {
    u64 d;
    asm("fma.rn.f32x2 %0, %1, %2, %3;" : "=l"(d) : "l"(a), "l"(b), "l"(c));
    return d;
}
__device__ __forceinline__ u64 fadd2(u64 a, u64 b) {
    u64 d;
    asm("add.rn.f32x2 %0, %1, %2;" : "=l"(d) : "l"(a), "l"(b));
    return d;
}
__device__ __forceinline__ float sigmoidf_(float x) { return 1.0f / (1.0f + expf(-x)); }
__device__ __forceinline__ float clip50(float x) { return fminf(fmaxf(x, -50.0f), 50.0f); }

// -------- state init (runs at graph start: deterministic across replays) --------
__global__ void init_states(const float* __restrict__ dh, const float* __restrict__ dc) {
    int idx = blockIdx.x * blockDim.x + threadIdx.x;   // 65536 total
    (&g_h[0][0][0][0])[idx] = dh[idx];
    (&g_c[0][0][0])[idx]    = dc[idx];
}

// -------- one LSTM layer-step --------
// grid: 128 blocks (4 hidden units each), 256 threads (8 warps).
// warp w: half = w>>2 (0: x@W_ih K-half, 1: h@W_hh K-half), gate = w&3, rows j0..j0+3.
// x||h staged in SMEM as batch-paired f32x2: xh2[b2][k], k in [0,1024).
__global__ __launch_bounds__(256) void lstm_step(
    int l, int t, int par,
    const float* __restrict__ emb, const int* __restrict__ target,
    const float* __restrict__ Wih, const float* __restrict__ Whh,
    const float* __restrict__ bih, const float* __restrict__ bhh)
{
    extern __shared__ u64 sm_[];
    u64* xh2 = sm_;                                  // [16][1024] u64 = 128KB
    float* gates_s = (float*)(sm_ + 16 * 1024);      // [2][4][4][32] = 4KB

    const int tid  = threadIdx.x;
    const int lane = tid & 31;
    const int wid  = tid >> 5;
    const int j0   = blockIdx.x * 4;

    const float* hsrc = &g_h[par][l][0][0];
    const float* xsrc = &g_xbuf[(l - 1) & 1][0][0];  // only valid for l>0

    // ---- stage x (k<512) and h_prev (k>=512) into SMEM as (b even, b odd) pairs ----
    #pragma unroll 4
    for (int idx = tid; idx < 16 * 1024; idx += 256) {
        int b2 = idx >> 10, k = idx & 1023;
        int b0 = b2 * 2, b1 = b0 + 1;
        float v0, v1;
        if (k < 512) {
            if (l == 0) {
                int t0 = (t == 0) ? 0 : target[b0 * NT + t - 1];
                int t1 = (t == 0) ? 0 : target[b1 * NT + t - 1];
                v0 = emb[t0 * 512 + k];
                v1 = emb[t1 * 512 + k];
            } else {
                v0 = xsrc[b0 * 512 + k];
                v1 = xsrc[b1 * 512 + k];
            }
        } else {
            v0 = hsrc[b0 * 512 + (k - 512)];
            v1 = hsrc[b1 * 512 + (k - 512)];
        }
        xh2[idx] = pk2(v0, v1);
    }
    __syncthreads();

    const int half = wid >> 2;
    const int gate = wid & 3;
    const float* Wsel = half ? Whh : Wih;
    const float* wbase[4];
    #pragma unroll
    for (int r = 0; r < 4; r++) {
        int n = gate * 512 + j0 + r;
        wbase[r] = Wsel + ((size_t)l * 2048 + n) * 512 + lane;
    }

    u64 acc[4][16];
    #pragma unroll
    for (int r = 0; r < 4; r++)
        #pragma unroll
        for (int b2 = 0; b2 < 16; b2++) acc[r][b2] = 0ULL;

    // ---- main dot-product loop over this warp's 512-wide K half, prefetching W ----
    float wc[4];
    #pragma unroll
    for (int r = 0; r < 4; r++) wc[r] = wbase[r][0];

    for (int kc = 0; kc < 16; kc++) {
        u64 aa[4];
        #pragma unroll
        for (int r = 0; r < 4; r++) aa[r] = pk2(wc[r], wc[r]);
        if (kc < 15) {
            #pragma unroll
            for (int r = 0; r < 4; r++) wc[r] = wbase[r][(kc + 1) * 32];
        }
        const u64* xrow = xh2 + (half * 512 + kc * 32 + lane);
        #pragma unroll
        for (int b2 = 0; b2 < 16; b2++) {
            u64 xv = xrow[b2 * 1024];
            #pragma unroll
            for (int r = 0; r < 4; r++) acc[r][b2] = ffma2(aa[r], xv, acc[r][b2]);
        }
    }

    // ---- cross-lane butterfly reduction (each lane held a k-slice) ----
    #pragma unroll
    for (int off = 16; off > 0; off >>= 1) {
        #pragma unroll
        for (int r = 0; r < 4; r++)
            #pragma unroll
            for (int b2 = 0; b2 < 16; b2++)
                acc[r][b2] = fadd2(acc[r][b2], __shfl_xor_sync(0xffffffffu, acc[r][b2], off));
    }

    if (lane < 16) {
        #pragma unroll
        for (int r = 0; r < 4; r++)
            *(u64*)&gates_s[(((half * 4 + gate) * 4) + r) * 32 + 2 * lane] = acc[r][lane];
    }
    __syncthreads();

    // ---- pointwise cell update: 4 j x 32 b = 128 elements ----
    if (tid < 128) {
        int jl = tid >> 5, b = tid & 31;
        int j = j0 + jl;
        float gv[4];
        #pragma unroll
        for (int g = 0; g < 4; g++) {
            int n = g * 512 + j;
            gv[g] = gates_s[((0 * 4 + g) * 4 + jl) * 32 + b]
                  + gates_s[((1 * 4 + g) * 4 + jl) * 32 + b]
                  + bih[l * 2048 + n] + bhh[l * 2048 + n];
        }
        float iv = sigmoidf_(gv[0]);
        float fv = sigmoidf_(gv[1]);
        float gg = tanhf(gv[2]);
        float ov = sigmoidf_(gv[3]);
        float cold = g_c[l][b][j];
        float cnew = fv * cold + iv * gg;
        float hnew = ov * tanhf(cnew);
        g_xbuf[l & 1][b][j] = hnew;                            // unclamped -> next layer
        if (l == 3) g_htop[((size_t)t * 32 + b) * 512 + j] = hnew;  // unclamped -> projection
        g_c[l][b][j] = clip50(cnew);                           // clamped carry
        g_h[par ^ 1][l][b][j] = clip50(hnew);                  // clamped carry (ping-pong)
    }
}

// -------- batched output projection: C[1664,32000] = htop @ Wout^T + bout --------
// BM=64, BN=128, 256 threads, per-thread 4m x 8n as 4x4 f32x2 accumulators.
__global__ __launch_bounds__(256) void proj_gemm(
    const float* __restrict__ Wout, const float* __restrict__ bout,
    float* __restrict__ out)
{
    __shared__ float As[32][64];     // [k][m]
    __shared__ float Bs[32][128];    // [k][n]
    const int tid = threadIdx.x;
    const int tx = tid & 15;
    const int ty = tid >> 4;
    const int bm = blockIdx.y * 64;
    const int bn = blockIdx.x * 128;

    u64 acc[4][4];
    #pragma unroll
    for (int i = 0; i < 4; i++)
        #pragma unroll
        for (int j = 0; j < 4; j++) acc[i][j] = 0ULL;

    for (int kt = 0; kt < 512; kt += 32) {
        __syncthreads();
        #pragma unroll
        for (int i = 0; i < 2; i++) {            // A tile: 64x32
            int s = tid + i * 256;
            int m = s >> 3, k4 = (s & 7) * 4;
            float4 v = *(const float4*)&g_htop[(size_t)(bm + m) * 512 + kt + k4];
            As[k4][m] = v.x; As[k4 + 1][m] = v.y; As[k4 + 2][m] = v.z; As[k4 + 3][m] = v.w;
        }
        #pragma unroll
        for (int i = 0; i < 4; i++) {            // B tile: 128x32
            int s = tid + i * 256;
            int n = s >> 3, k4 = (s & 7) * 4;
            float4 v = *(const float4*)&Wout[(size_t)(bn + n) * 512 + kt + k4];
            Bs[k4][n] = v.x; Bs[k4 + 1][n] = v.y; Bs[k4 + 2][n] = v.z; Bs[k4 + 3][n] = v.w;
        }
        __syncthreads();
        #pragma unroll
        for (int kk = 0; kk < 32; kk++) {
            float4 a4 = *(const float4*)&As[kk][ty * 4];
            u64 bv[4];
            #pragma unroll
            for (int jj = 0; jj < 4; jj++)       // n-pairs at stride 16 u64 -> conflict-free
                bv[jj] = *(const u64*)&Bs[kk][2 * tx + 32 * jj];
            u64 aa;
            aa = pk2(a4.x, a4.x);
            #pragma unroll
            for (int jj = 0; jj < 4; jj++) acc[0][jj] = ffma2(aa, bv[jj], acc[0][jj]);
            aa = pk2(a4.y, a4.y);
            #pragma unroll
            for (int jj = 0; jj < 4; jj++) acc[1][jj] = ffma2(aa, bv[jj], acc[1][jj]);
            aa = pk2(a4.z, a4.z);
            #pragma unroll
            for (int jj = 0; jj < 4; jj++) acc[2][jj] = ffma2(aa, bv[jj], acc[2][jj]);
            aa = pk2(a4.w, a4.w);
            #pragma unroll
            for (int jj = 0; jj < 4; jj++) acc[3][jj] = ffma2(aa, bv[jj], acc[3][jj]);
        }
    }

    #pragma unroll
    for (int i = 0; i < 4; i++) {
        int r = bm + ty * 4 + i;                 // r = t*32 + b
        if (r < 1632) {
            int tt = r >> 5, b = r & 31;
            size_t rowbase = (size_t)b * NT * NV + (size_t)tt * NV;
            #pragma unroll
            for (int jj = 0; jj < 4; jj++) {
                int n = bn + 2 * tx + 32 * jj;
                float lo, hi; upk2(acc[i][jj], lo, hi);
                float2 bo = *(const float2*)&bout[n];
                float2 res = make_float2(lo + bo.x, hi + bo.y);
                *(float2*)&out[rowbase + n] = res;
            }
        }
    }
}

// -------- final hidden state -> tail of d_out --------
__global__ void write_hfin(float* __restrict__ out) {
    int idx = blockIdx.x * blockDim.x + threadIdx.x;   // 65536
    out[(size_t)NB * NT * NV + idx] = (&g_h[1][0][0][0])[idx];
}

extern "C" void kernel_launch(void* const* d_in, const int* in_sizes, int n_in,
                              void* d_out, int out_size)
{
    (void)in_sizes; (void)n_in; (void)out_size;
    // metadata order: encoder_output, decoder_hidden, decoder_cell, target_tensor,
    //                 embedding, W_ih, W_hh, b_ih, b_hh, W_out, b_out
    const float* dh   = (const float*)d_in[1];
    const float* dc   = (const float*)d_in[2];
    const int*   tgt  = (const int*)  d_in[3];
    const float* emb  = (const float*)d_in[4];
    const float* Wih  = (const float*)d_in[5];
    const float* Whh  = (const float*)d_in[6];
    const float* bih  = (const float*)d_in[7];
    const float* bhh  = (const float*)d_in[8];
    const float* Wout = (const float*)d_in[9];
    const float* bout = (const float*)d_in[10];
    float* out = (float*)d_out;

    const int SMEM_LSTM = 16 * 1024 * 8 + 2 * 4 * 4 * 32 * 4;   // 135168 B
    cudaFuncSetAttribute(lstm_step, cudaFuncAttributeMaxDynamicSharedMemorySize, SMEM_LSTM);

    init_states<<<256, 256>>>(dh, dc);

    for (int t = 0; t < NT; t++)
        for (int l = 0; l < NL; l++)
            lstm_step<<<128, 256, SMEM_LSTM>>>(l, t, t & 1, emb, tgt, Wih, Whh, bih, bhh);

    proj_gemm<<<dim3(250, 26), 256>>>(Wout, bout, out);
    write_hfin<<<256, 256>>>(out);
}

// round 3
// speedup vs baseline: 2.1758x; 2.1758x over previous
#include <cuda_runtime.h>
#include <math.h>

#define NL 4
#define NB 32
#define NH 512
#define NV 32000
#define NT 51

typedef unsigned long long u64;

// -------- persistent device scratch --------
// All activations stored as batch-paired f32x2: [b2][k], b2 pairs batches (2*b2, 2*b2+1).
__device__ u64 g_x[2][NL][16][512];      // layer-input x pairs (l>=1), ping-pong by t parity
__device__ u64 g_hb[2][NL][16][512];     // clamped hidden pairs, ping-pong by t parity
__device__ u64 g_c2[NL][16][512];        // clamped cell pairs (no hazard: unique l per diagonal)
__device__ u64 g_emb2[NT][16][512];      // pre-gathered embedding pairs per timestep
__device__ float g_htop[1664 * NH];      // top-layer hidden per step (scalar layout for proj)

// -------- packed f32x2 helpers --------
__device__ __forceinline__ u64 pk2(float lo, float hi) {
    u64 r;
    asm("mov.b64 %0, {%1, %2};" : "=l"(r) : "r"(__float_as_uint(lo)), "r"(__float_as_uint(hi)));
    return r;
}
__device__ __forceinline__ void upk2(u64 v, float &lo, float &hi) {
    unsigned a, b;
    asm("mov.b64 {%0, %1}, %2;" : "=r"(a), "=r"(b) : "l"(v));
    lo = __uint_as_float(a); hi = __uint_as_float(b);
}
__device__ __forceinline__ u64 ffma2(u64 a, u64 b, u64 c) {
    u64 d;
    asm("fma.rn.f32x2 %0, %1, %2, %3;" : "=l"(d) : "l"(a), "l"(b), "l"(c));
    return d;
}
__device__ __forceinline__ u64 fadd2(u64 a, u64 b) {
    u64 d;
    asm("add.rn.f32x2 %0, %1, %2;" : "=l"(d) : "l"(a), "l"(b));
    return d;
}
__device__ __forceinline__ float sigmoidf_(float x) { return 1.0f / (1.0f + expf(-x)); }
__device__ __forceinline__ float clip50(float x) { return fminf(fmaxf(x, -50.0f), 50.0f); }

// -------- init: pack h0/c0 into pairs --------
__global__ void init_pair(const float* __restrict__ dh, const float* __restrict__ dc) {
    int idx = blockIdx.x * blockDim.x + threadIdx.x;   // 32768
    int l = idx >> 13, rem = idx & 8191, b2 = rem >> 9, j = rem & 511;
    int b0 = 2 * b2, b1 = b0 + 1;
    g_hb[0][l][b2][j] = pk2(dh[(l * 32 + b0) * 512 + j], dh[(l * 32 + b1) * 512 + j]);
    g_c2[l][b2][j]    = pk2(dc[(l * 32 + b0) * 512 + j], dc[(l * 32 + b1) * 512 + j]);
}

// -------- init: pre-gather teacher-forced embedding pairs for all timesteps --------
__global__ void init_emb(const float* __restrict__ emb, const int* __restrict__ target) {
    int idx = blockIdx.x * blockDim.x + threadIdx.x;   // 51*8192 = 417792
    if (idx >= NT * 8192) return;
    int t = idx >> 13, rem = idx & 8191, b2 = rem >> 9, k = rem & 511;
    int b0 = 2 * b2, b1 = b0 + 1;
    int t0 = (t == 0) ? 0 : target[b0 * NT + t - 1];
    int t1 = (t == 0) ? 0 : target[b1 * NT + t - 1];
    g_emb2[t][b2][k] = pk2(emb[t0 * 512 + k], emb[t1 * 512 + k]);
}

// -------- wavefront LSTM: all independent (t,l) stages on diagonal d = t + l --------
// Per stage: 128 blocks x 512 threads. Block owns 4 hidden units (16 gate rows).
// Warp tile: 4 rows x 8 batch-pairs x 512-K-half, lane-split K by 32.
__global__ __launch_bounds__(512) void lstm_diag(
    int d,
    const float* __restrict__ Wih, const float* __restrict__ Whh,
    const float* __restrict__ bih, const float* __restrict__ bhh)
{
    extern __shared__ u64 sm_[];
    u64* xh2 = sm_;                        // [16][1024] u64 = 128KB, layout [b2][k]
    u64* gates2 = sm_ + 16 * 1024;         // [2 khalf][4 gate][4 r][16 b2] u64 = 2KB

    const int lmin = (d > NT - 1) ? d - (NT - 1) : 0;
    const int l = lmin + (blockIdx.x >> 7);
    const int t = d - l;
    const int par = t & 1;
    const int j0 = (blockIdx.x & 127) * 4;
    const int tid = threadIdx.x, lane = tid & 31, wid = tid >> 5;

    // ---- stage x-half and h-half (pure coalesced copies, already paired) ----
    const float4* xsrc = (const float4*)((l == 0) ? &g_emb2[t][0][0] : &g_x[par][l][0][0]);
    const float4* hsrc = (const float4*)&g_hb[par][l][0][0];
    float4* xh4 = (float4*)xh2;
    #pragma unroll
    for (int i = 0; i < 8; i++) {
        int idx = i * 512 + tid;           // 0..4095 float4 per half
        int b2 = idx >> 8, off = idx & 255;
        xh4[b2 * 512 + off]       = xsrc[idx];
        xh4[b2 * 512 + 256 + off] = hsrc[idx];
    }
    __syncthreads();

    // ---- gate GEMM ----
    const int khalf = wid & 1;
    const int gate  = (wid >> 1) & 3;
    const int bhalf = (wid >> 3) & 1;
    const float* wp = (khalf ? Whh : Wih) + ((size_t)(l * 2048 + gate * 512 + j0)) * 512 + lane;
    const u64* xb = xh2 + (bhalf * 8) * 1024 + khalf * 512 + lane;

    u64 acc[4][8];
    #pragma unroll
    for (int r = 0; r < 4; r++)
        #pragma unroll
        for (int b = 0; b < 8; b++) acc[r][b] = 0ULL;

    float wc[4];
    #pragma unroll
    for (int r = 0; r < 4; r++) wc[r] = wp[r * 512];

    for (int kc = 0; kc < 16; kc++) {
        u64 aa[4];
        #pragma unroll
        for (int r = 0; r < 4; r++) aa[r] = pk2(wc[r], wc[r]);
        if (kc < 15) {
            #pragma unroll
            for (int r = 0; r < 4; r++) wc[r] = wp[r * 512 + (kc + 1) * 32];
        }
        #pragma unroll
        for (int b = 0; b < 8; b++) {
            u64 xv = xb[b * 1024 + kc * 32];
            #pragma unroll
            for (int r = 0; r < 4; r++) acc[r][b] = ffma2(aa[r], xv, acc[r][b]);
        }
    }

    // ---- butterfly reduction over the 32 k-slices ----
    #pragma unroll
    for (int off = 16; off > 0; off >>= 1) {
        #pragma unroll
        for (int r = 0; r < 4; r++)
            #pragma unroll
            for (int b = 0; b < 8; b++)
                acc[r][b] = fadd2(acc[r][b], __shfl_xor_sync(0xffffffffu, acc[r][b], off));
    }
    if (lane == 0) {
        #pragma unroll
        for (int r = 0; r < 4; r++)
            #pragma unroll
            for (int b = 0; b < 8; b++)
                gates2[(((khalf * 4 + gate) * 4) + r) * 16 + bhalf * 8 + b] = acc[r][b];
    }
    __syncthreads();

    // ---- pointwise epilogue: 4 j x 16 b2 = 64 threads, each handles a batch pair ----
    if (tid < 64) {
        int jl = tid >> 4, b2 = tid & 15;
        int j = j0 + jl;
        float gv0[4], gv1[4];
        #pragma unroll
        for (int g = 0; g < 4; g++) {
            u64 s = fadd2(gates2[((0 * 4 + g) * 4 + jl) * 16 + b2],
                          gates2[((1 * 4 + g) * 4 + jl) * 16 + b2]);
            float lo, hi; upk2(s, lo, hi);
            float bb = bih[l * 2048 + g * 512 + j] + bhh[l * 2048 + g * 512 + j];
            gv0[g] = lo + bb; gv1[g] = hi + bb;
        }
        float c0, c1; upk2(g_c2[l][b2][j], c0, c1);

        float i0 = sigmoidf_(gv0[0]), f0 = sigmoidf_(gv0[1]);
        float gg0 = tanhf(gv0[2]),   o0 = sigmoidf_(gv0[3]);
        float cn0 = f0 * c0 + i0 * gg0;
        float h0 = o0 * tanhf(cn0);

        float i1 = sigmoidf_(gv1[0]), f1 = sigmoidf_(gv1[1]);
        float gg1 = tanhf(gv1[2]),   o1 = sigmoidf_(gv1[3]);
        float cn1 = f1 * c1 + i1 * gg1;
        float h1 = o1 * tanhf(cn1);

        if (l < 3) {
            g_x[par][l + 1][b2][j] = pk2(h0, h1);         // unclamped -> next layer, same step
        } else {
            int b0 = 2 * b2;
            g_htop[((size_t)t * 32 + b0) * 512 + j] = h0; // unclamped -> projection
            g_htop[((size_t)t * 32 + b0 + 1) * 512 + j] = h1;
        }
        g_hb[par ^ 1][l][b2][j] = pk2(clip50(h0), clip50(h1));  // clamped carry -> t+1
        g_c2[l][b2][j] = pk2(clip50(cn0), clip50(cn1));
    }
}

// -------- batched output projection: C[1664,32000] = htop @ Wout^T + bout --------
__global__ __launch_bounds__(256) void proj_gemm(
    const float* __restrict__ Wout, const float* __restrict__ bout,
    float* __restrict__ out)
{
    __shared__ float As[32][64];     // [k][m]
    __shared__ float Bs[32][128];    // [k][n]
    const int tid = threadIdx.x;
    const int tx = tid & 15;
    const int ty = tid >> 4;
    const int bm = blockIdx.y * 64;
    const int bn = blockIdx.x * 128;

    u64 acc[4][4];
    #pragma unroll
    for (int i = 0; i < 4; i++)
        #pragma unroll
        for (int j = 0; j < 4; j++) acc[i][j] = 0ULL;

    for (int kt = 0; kt < 512; kt += 32) {
        __syncthreads();
        #pragma unroll
        for (int i = 0; i < 2; i++) {            // A tile: 64x32
            int s = tid + i * 256;
            int m = s >> 3, k4 = (s & 7) * 4;
            float4 v = *(const float4*)&g_htop[(size_t)(bm + m) * 512 + kt + k4];
            As[k4][m] = v.x; As[k4 + 1][m] = v.y; As[k4 + 2][m] = v.z; As[k4 + 3][m] = v.w;
        }
        #pragma unroll
        for (int i = 0; i < 4; i++) {            // B tile: 128x32
            int s = tid + i * 256;
            int n = s >> 3, k4 = (s & 7) * 4;
            float4 v = *(const float4*)&Wout[(size_t)(bn + n) * 512 + kt + k4];
            Bs[k4][n] = v.x; Bs[k4 + 1][n] = v.y; Bs[k4 + 2][n] = v.z; Bs[k4 + 3][n] = v.w;
        }
        __syncthreads();
        #pragma unroll
        for (int kk = 0; kk < 32; kk++) {
            float4 a4 = *(const float4*)&As[kk][ty * 4];
            u64 bv[4];
            #pragma unroll
            for (int jj = 0; jj < 4; jj++)
                bv[jj] = *(const u64*)&Bs[kk][2 * tx + 32 * jj];
            u64 aa;
            aa = pk2(a4.x, a4.x);
            #pragma unroll
            for (int jj = 0; jj < 4; jj++) acc[0][jj] = ffma2(aa, bv[jj], acc[0][jj]);
            aa = pk2(a4.y, a4.y);
            #pragma unroll
            for (int jj = 0; jj < 4; jj++) acc[1][jj] = ffma2(aa, bv[jj], acc[1][jj]);
            aa = pk2(a4.z, a4.z);
            #pragma unroll
            for (int jj = 0; jj < 4; jj++) acc[2][jj] = ffma2(aa, bv[jj], acc[2][jj]);
            aa = pk2(a4.w, a4.w);
            #pragma unroll
            for (int jj = 0; jj < 4; jj++) acc[3][jj] = ffma2(aa, bv[jj], acc[3][jj]);
        }
    }

    #pragma unroll
    for (int i = 0; i < 4; i++) {
        int r = bm + ty * 4 + i;                 // r = t*32 + b
        if (r < 1632) {
            int tt = r >> 5, b = r & 31;
            size_t rowbase = (size_t)b * NT * NV + (size_t)tt * NV;
            #pragma unroll
            for (int jj = 0; jj < 4; jj++) {
                int n = bn + 2 * tx + 32 * jj;
                float lo, hi; upk2(acc[i][jj], lo, hi);
                float2 bo = *(const float2*)&bout[n];
                float2 res = make_float2(lo + bo.x, hi + bo.y);
                *(float2*)&out[rowbase + n] = res;
            }
        }
    }
}

// -------- final hidden state -> tail of d_out (unpack pairs) --------
__global__ void write_hfin(float* __restrict__ out) {
    int idx = blockIdx.x * blockDim.x + threadIdx.x;   // 65536
    int l = idx >> 14, b = (idx >> 9) & 31, j = idx & 511;
    float lo, hi; upk2(g_hb[1][l][b >> 1][j], lo, hi);
    out[(size_t)NB * NT * NV + idx] = (b & 1) ? hi : lo;
}

extern "C" void kernel_launch(void* const* d_in, const int* in_sizes, int n_in,
                              void* d_out, int out_size)
{
    (void)in_sizes; (void)n_in; (void)out_size;
    const float* dh   = (const float*)d_in[1];
    const float* dc   = (const float*)d_in[2];
    const int*   tgt  = (const int*)  d_in[3];
    const float* emb  = (const float*)d_in[4];
    const float* Wih  = (const float*)d_in[5];
    const float* Whh  = (const float*)d_in[6];
    const float* bih  = (const float*)d_in[7];
    const float* bhh  = (const float*)d_in[8];
    const float* Wout = (const float*)d_in[9];
    const float* bout = (const float*)d_in[10];
    float* out = (float*)d_out;

    const int SMEM_LSTM = 16 * 1024 * 8 + 2 * 4 * 4 * 16 * 8;   // 133120 B
    cudaFuncSetAttribute(lstm_diag, cudaFuncAttributeMaxDynamicSharedMemorySize, SMEM_LSTM);

    init_pair<<<128, 256>>>(dh, dc);
    init_emb<<<1632, 256>>>(emb, tgt);

    for (int d = 0; d < NT + NL - 1; d++) {
        int lmin = (d > NT - 1) ? d - (NT - 1) : 0;
        int lmax = (d < NL - 1) ? d : NL - 1;
        int ns = lmax - lmin + 1;
        lstm_diag<<<128 * ns, 512, SMEM_LSTM>>>(d, Wih, Whh, bih, bhh);
    }

    proj_gemm<<<dim3(250, 26), 256>>>(Wout, bout, out);
    write_hfin<<<256, 256>>>(out);
}

// round 5
// speedup vs baseline: 4.0609x; 1.8664x over previous
#include <cuda_runtime.h>
#include <cuda_bf16.h>
#include <math.h>
#include <stdint.h>

#define NL 4
#define NB 32
#define NH 512
#define NV 32000
#define NTT 51

typedef unsigned long long u64;

// ================= persistent device scratch =================
__device__ u64 g_x[2][NL][16][512];      // layer-input pairs (l>=1), ping-pong by t parity
__device__ u64 g_hb[2][NL][16][512];     // clamped hidden pairs, ping-pong by t parity
__device__ u64 g_c2[NL][16][512];        // clamped cell pairs
__device__ u64 g_emb2[NTT][16][512];     // pre-gathered embedding pairs per timestep
__device__ float g_htop[1664 * NH];      // top-layer hidden per step (pad rows stay 0)

// bf16 hi/lo splits, row-major [row][512]
__device__ __nv_bfloat16 g_Hs[2][1664 * 512];
__device__ __nv_bfloat16 g_Ws[2][NV * 512];

// ================= helpers =================
__device__ __forceinline__ u64 pk2(float lo, float hi) {
    u64 r;
    asm("mov.b64 %0, {%1, %2};" : "=l"(r) : "r"(__float_as_uint(lo)), "r"(__float_as_uint(hi)));
    return r;
}
__device__ __forceinline__ void upk2(u64 v, float &lo, float &hi) {
    unsigned a, b;
    asm("mov.b64 {%0, %1}, %2;" : "=r"(a), "=r"(b) : "l"(v));
    lo = __uint_as_float(a); hi = __uint_as_float(b);
}
__device__ __forceinline__ u64 ffma2(u64 a, u64 b, u64 c) {
    u64 d;
    asm("fma.rn.f32x2 %0, %1, %2, %3;" : "=l"(d) : "l"(a), "l"(b), "l"(c));
    return d;
}
__device__ __forceinline__ u64 fadd2(u64 a, u64 b) {
    u64 d;
    asm("add.rn.f32x2 %0, %1, %2;" : "=l"(d) : "l"(a), "l"(b));
    return d;
}
__device__ __forceinline__ float sigmoidf_(float x) { return 1.0f / (1.0f + expf(-x)); }
__device__ __forceinline__ float clip50(float x) { return fminf(fmaxf(x, -50.0f), 50.0f); }

__device__ __forceinline__ uint32_t s2u(const void* p) {
    return (uint32_t)__cvta_generic_to_shared(p);
}
__device__ __forceinline__ void mbar_init(uint32_t mbar, uint32_t cnt) {
    asm volatile("mbarrier.init.shared.b64 [%0], %1;" :: "r"(mbar), "r"(cnt) : "memory");
}
__device__ __forceinline__ void mbar_expect_tx(uint32_t mbar, uint32_t bytes) {
    asm volatile("mbarrier.arrive.expect_tx.shared.b64 _, [%0], %1;" :: "r"(mbar), "r"(bytes) : "memory");
}
__device__ __forceinline__ void mbar_wait(uint32_t mbar, uint32_t parity) {
    asm volatile("{\n\t.reg .pred P1;\nLW%=:\n\t"
                 "mbarrier.try_wait.parity.shared::cta.b64 P1, [%0], %1;\n\t"
                 "@!P1 bra LW%=;\n}"
                 :: "r"(mbar), "r"(parity) : "memory");
}
__device__ __forceinline__ void bulk_cp(uint32_t dst, const void* src, uint32_t bytes, uint32_t mbar) {
    asm volatile("cp.async.bulk.shared::cluster.global.mbarrier::complete_tx::bytes [%0], [%1], %2, [%3];"
                 :: "r"(dst), "l"(src), "r"(bytes), "r"(mbar) : "memory");
}
__device__ __forceinline__ void cpasync16(uint32_t dst, const void* src) {
    asm volatile("cp.async.cg.shared.global [%0], [%1], 16;" :: "r"(dst), "l"(src));
}
__device__ __forceinline__ void cp_commit() { asm volatile("cp.async.commit_group;" ::: "memory"); }
__device__ __forceinline__ void cp_wait1() { asm volatile("cp.async.wait_group 1;" ::: "memory"); }

#define LDMX4(r0, r1, r2, r3, a) \
    asm volatile("ldmatrix.sync.aligned.m8n8.x4.shared.b16 {%0,%1,%2,%3}, [%4];" \
                 : "=r"(r0), "=r"(r1), "=r"(r2), "=r"(r3) : "r"(a))

__device__ __forceinline__ void mma16816(float* d, const uint32_t* a, const uint32_t* b) {
    asm volatile("mma.sync.aligned.m16n8k16.row.col.f32.bf16.bf16.f32 "
                 "{%0,%1,%2,%3}, {%4,%5,%6,%7}, {%8,%9}, {%0,%1,%2,%3};"
                 : "+f"(d[0]), "+f"(d[1]), "+f"(d[2]), "+f"(d[3])
                 : "r"(a[0]), "r"(a[1]), "r"(a[2]), "r"(a[3]), "r"(b[0]), "r"(b[1]));
}

// ================= init kernels =================
__global__ void init_pair(const float* __restrict__ dh, const float* __restrict__ dc) {
    int idx = blockIdx.x * blockDim.x + threadIdx.x;   // 32768
    int l = idx >> 13, rem = idx & 8191, b2 = rem >> 9, j = rem & 511;
    int b0 = 2 * b2, b1 = b0 + 1;
    g_hb[0][l][b2][j] = pk2(dh[(l * 32 + b0) * 512 + j], dh[(l * 32 + b1) * 512 + j]);
    g_c2[l][b2][j]    = pk2(dc[(l * 32 + b0) * 512 + j], dc[(l * 32 + b1) * 512 + j]);
}

__global__ void init_emb(const float* __restrict__ emb, const int* __restrict__ target) {
    int idx = blockIdx.x * blockDim.x + threadIdx.x;   // 51*8192
    if (idx >= NTT * 8192) return;
    int t = idx >> 13, rem = idx & 8191, b2 = rem >> 9, k = rem & 511;
    int b0 = 2 * b2, b1 = b0 + 1;
    int t0 = (t == 0) ? 0 : target[b0 * NTT + t - 1];
    int t1 = (t == 0) ? 0 : target[b1 * NTT + t - 1];
    g_emb2[t][b2][k] = pk2(emb[t0 * 512 + k], emb[t1 * 512 + k]);
}

// split W_out / htop into hi+lo bf16 (row-major)
__global__ void conv_w(const float* __restrict__ W) {
    int idx = blockIdx.x * blockDim.x + threadIdx.x;   // 32000*64
    if (idx >= NV * 64) return;
    size_t base = (size_t)idx * 8;
    const float4* s = (const float4*)(W + base);
    float4 a = s[0], b = s[1];
    float v[8] = {a.x, a.y, a.z, a.w, b.x, b.y, b.z, b.w};
    __align__(16) __nv_bfloat16 hi[8], lo[8];
    #pragma unroll
    for (int i = 0; i < 8; i++) {
        hi[i] = __float2bfloat16_rn(v[i]);
        lo[i] = __float2bfloat16_rn(v[i] - __bfloat162float(hi[i]));
    }
    *(uint4*)&g_Ws[0][base] = *(const uint4*)hi;
    *(uint4*)&g_Ws[1][base] = *(const uint4*)lo;
}

__global__ void conv_h() {
    int idx = blockIdx.x * blockDim.x + threadIdx.x;   // 1664*64
    if (idx >= 1664 * 64) return;
    size_t base = (size_t)idx * 8;
    const float4* s = (const float4*)(g_htop + base);
    float4 a = s[0], b = s[1];
    float v[8] = {a.x, a.y, a.z, a.w, b.x, b.y, b.z, b.w};
    __align__(16) __nv_bfloat16 hi[8], lo[8];
    #pragma unroll
    for (int i = 0; i < 8; i++) {
        hi[i] = __float2bfloat16_rn(v[i]);
        lo[i] = __float2bfloat16_rn(v[i] - __bfloat162float(hi[i]));
    }
    *(uint4*)&g_Hs[0][base] = *(const uint4*)hi;
    *(uint4*)&g_Hs[1][base] = *(const uint4*)lo;
}

// ================= wavefront LSTM =================
// Per stage: 256 blocks (128 j-tiles x 2 batch-halves), 256 threads (8 warps).
__global__ __launch_bounds__(256) void lstm_diag(
    int d,
    const float* __restrict__ Wih, const float* __restrict__ Whh,
    const float* __restrict__ bih, const float* __restrict__ bhh)
{
    extern __shared__ u64 sm_[];
    u64* xh2 = sm_;                        // [2 khalf][8 b2][512] u64 = 64KB
    u64* gates2 = sm_ + 8192;              // [2][4][4][8] u64 = 2KB
    u64* mbar_st = sm_ + 8192 + 256;

    const int lmin = (d > NTT - 1) ? d - (NTT - 1) : 0;
    const int within = blockIdx.x & 255;
    const int l = lmin + (blockIdx.x >> 8);
    const int t = d - l;
    const int par = t & 1;
    const int bhalf = within >> 7;
    const int j0 = (within & 127) * 4;
    const int tid = threadIdx.x, lane = tid & 31, wid = tid >> 5;

    uint32_t mbar = s2u(mbar_st);
    if (tid == 0) mbar_init(mbar, 1);
    __syncthreads();
    if (tid == 0) {
        const u64* xsrc = ((l == 0) ? &g_emb2[t][0][0] : &g_x[par][l][0][0]) + bhalf * 4096;
        const u64* hsrc = &g_hb[par][l][0][0] + bhalf * 4096;
        mbar_expect_tx(mbar, 65536);
        bulk_cp(s2u(xh2), xsrc, 32768, mbar);
        bulk_cp(s2u(xh2 + 4096), hsrc, 32768, mbar);
    }

    const int khalf = wid & 1;
    const int gate  = (wid >> 1) & 3;
    const float* wp = (khalf ? Whh : Wih) + ((size_t)(l * 2048 + gate * 512 + j0)) * 512 + lane;
    float wc[4];
    #pragma unroll
    for (int r = 0; r < 4; r++) wc[r] = wp[r * 512];

    mbar_wait(mbar, 0);

    const u64* xb = xh2 + khalf * 4096 + lane;
    u64 acc[4][8];
    #pragma unroll
    for (int r = 0; r < 4; r++)
        #pragma unroll
        for (int b = 0; b < 8; b++) acc[r][b] = 0ULL;

    for (int kc = 0; kc < 16; kc++) {
        u64 aa[4];
        #pragma unroll
        for (int r = 0; r < 4; r++) aa[r] = pk2(wc[r], wc[r]);
        if (kc < 15) {
            #pragma unroll
            for (int r = 0; r < 4; r++) wc[r] = wp[r * 512 + (kc + 1) * 32];
        }
        #pragma unroll
        for (int b = 0; b < 8; b++) {
            u64 xv = xb[b * 512 + kc * 32];
            #pragma unroll
            for (int r = 0; r < 4; r++) acc[r][b] = ffma2(aa[r], xv, acc[r][b]);
        }
    }

    #pragma unroll
    for (int off = 16; off > 0; off >>= 1) {
        #pragma unroll
        for (int r = 0; r < 4; r++)
            #pragma unroll
            for (int b = 0; b < 8; b++)
                acc[r][b] = fadd2(acc[r][b], __shfl_xor_sync(0xffffffffu, acc[r][b], off));
    }
    if (lane == 0) {
        #pragma unroll
        for (int r = 0; r < 4; r++)
            #pragma unroll
            for (int b = 0; b < 8; b++)
                gates2[(((khalf * 4 + gate) * 4) + r) * 8 + b] = acc[r][b];
    }
    __syncthreads();

    if (tid < 32) {
        int jl = tid >> 3, b2l = tid & 7;
        int b2 = bhalf * 8 + b2l;
        int j = j0 + jl;
        float gv0[4], gv1[4];
        #pragma unroll
        for (int g = 0; g < 4; g++) {
            u64 s = fadd2(gates2[((0 * 4 + g) * 4 + jl) * 8 + b2l],
                          gates2[((1 * 4 + g) * 4 + jl) * 8 + b2l]);
            float lo, hi; upk2(s, lo, hi);
            float bb = bih[l * 2048 + g * 512 + j] + bhh[l * 2048 + g * 512 + j];
            gv0[g] = lo + bb; gv1[g] = hi + bb;
        }
        float c0, c1; upk2(g_c2[l][b2][j], c0, c1);

        float i0 = sigmoidf_(gv0[0]), f0 = sigmoidf_(gv0[1]);
        float gg0 = tanhf(gv0[2]),   o0 = sigmoidf_(gv0[3]);
        float cn0 = f0 * c0 + i0 * gg0;
        float h0 = o0 * tanhf(cn0);

        float i1 = sigmoidf_(gv1[0]), f1 = sigmoidf_(gv1[1]);
        float gg1 = tanhf(gv1[2]),   o1 = sigmoidf_(gv1[3]);
        float cn1 = f1 * c1 + i1 * gg1;
        float h1 = o1 * tanhf(cn1);

        if (l < 3) {
            g_x[par][l + 1][b2][j] = pk2(h0, h1);
        } else {
            int b0 = 2 * b2;
            g_htop[((size_t)t * 32 + b0) * 512 + j] = h0;
            g_htop[((size_t)t * 32 + b0 + 1) * 512 + j] = h1;
        }
        g_hb[par ^ 1][l][b2][j] = pk2(clip50(h0), clip50(h1));
        g_c2[l][b2][j] = pk2(clip50(cn0), clip50(cn1));
    }
}

// ================= mma.sync bf16 projection =================
// C[1664,32000] = sum of 3 passes (Ahi Bhi, Ahi Blo, Alo Bhi), K=512 each.
// BM=BN=128, BK=64 (128B rows, XOR swizzle), 8 warps (4m x 2n), warp tile 32x64.
// SMEM: A[2][16KB] @0, B[2][16KB] @32768. 64KB dynamic.
__global__ __launch_bounds__(256) void proj_mma(
    const float* __restrict__ bout, float* __restrict__ out)
{
    extern __shared__ __align__(16) unsigned char ps[];
    const uint32_t sb = s2u(ps);
    const int tid = threadIdx.x, lane = tid & 31, wid = tid >> 5;
    const int wm = wid & 3, wn = wid >> 2;
    const int bm = blockIdx.y * 128, bn = blockIdx.x * 128;

    const uint32_t Ab[2] = {sb, sb + 16384};
    const uint32_t Bb[2] = {sb + 32768, sb + 49152};
    const int pA[3] = {0, 0, 1};
    const int pB[3] = {0, 1, 0};

    float acc[2][8][4];
    #pragma unroll
    for (int f = 0; f < 2; f++)
        #pragma unroll
        for (int p = 0; p < 8; p++)
            #pragma unroll
            for (int q = 0; q < 4; q++) acc[f][p][q] = 0.0f;

    // staging lambda-ish
    const int sr = tid >> 3, su = tid & 7;   // thread's 4 rows: sr, sr+32, sr+64, sr+96

    // prologue: chunk 0
    {
        const __nv_bfloat16* Ag = g_Hs[0];
        const __nv_bfloat16* Bg = g_Ws[0];
        #pragma unroll
        for (int i = 0; i < 4; i++) {
            int r = sr + i * 32;
            cpasync16(Ab[0] + r * 128 + ((su ^ (r & 7)) << 4),
                      Ag + (size_t)(bm + r) * 512 + su * 8);
            cpasync16(Bb[0] + r * 128 + ((su ^ (r & 7)) << 4),
                      Bg + (size_t)(bn + r) * 512 + su * 8);
        }
    }
    cp_commit();

    for (int c = 0; c < 24; c++) {
        if (c + 1 < 24) {
            int c2 = c + 1, pass = c2 >> 3, k0 = (c2 & 7) * 64;
            const __nv_bfloat16* Ag = g_Hs[pA[pass]];
            const __nv_bfloat16* Bg = g_Ws[pB[pass]];
            uint32_t da = Ab[c2 & 1], db = Bb[c2 & 1];
            #pragma unroll
            for (int i = 0; i < 4; i++) {
                int r = sr + i * 32;
                cpasync16(da + r * 128 + ((su ^ (r & 7)) << 4),
                          Ag + (size_t)(bm + r) * 512 + k0 + su * 8);
                cpasync16(db + r * 128 + ((su ^ (r & 7)) << 4),
                          Bg + (size_t)(bn + r) * 512 + k0 + su * 8);
            }
        }
        cp_commit();
        cp_wait1();
        __syncthreads();

        const uint32_t Abase = Ab[c & 1], Bbase = Bb[c & 1];
        const int jA = lane >> 3;
        #pragma unroll
        for (int q = 0; q < 4; q++) {
            uint32_t a[2][4];
            #pragma unroll
            for (int f = 0; f < 2; f++) {
                int r = wm * 32 + f * 16 + (lane & 7) + ((jA & 1) << 3);
                int u = 2 * q + (jA >> 1);
                uint32_t ad = Abase + r * 128 + ((u ^ (r & 7)) << 4);
                LDMX4(a[f][0], a[f][1], a[f][2], a[f][3], ad);
            }
            uint32_t b[8][2];
            #pragma unroll
            for (int fp = 0; fp < 4; fp++) {
                int r = wn * 64 + fp * 16 + (lane & 7) + ((jA >> 1) << 3);
                int u = 2 * q + (jA & 1);
                uint32_t bd = Bbase + r * 128 + ((u ^ (r & 7)) << 4);
                LDMX4(b[2 * fp][0], b[2 * fp][1], b[2 * fp + 1][0], b[2 * fp + 1][1], bd);
            }
            #pragma unroll
            for (int f = 0; f < 2; f++)
                #pragma unroll
                for (int p = 0; p < 8; p++)
                    mma16816(acc[f][p], a[f], b[p]);
        }
        __syncthreads();
    }

    // epilogue: C[m][n] + bias, remap m=(t*32+b) -> out[b][t][:]
    #pragma unroll
    for (int f = 0; f < 2; f++) {
        int m0 = bm + wm * 32 + f * 16 + (lane >> 2);
        #pragma unroll
        for (int p = 0; p < 8; p++) {
            int n = bn + wn * 64 + p * 8 + 2 * (lane & 3);
            float2 bo = *(const float2*)&bout[n];
            int m = m0;
            if (m < 1632) {
                int tt = m >> 5, b = m & 31;
                float2 r0 = make_float2(acc[f][p][0] + bo.x, acc[f][p][1] + bo.y);
                *(float2*)&out[(size_t)b * NTT * NV + (size_t)tt * NV + n] = r0;
            }
            m = m0 + 8;
            if (m < 1632) {
                int tt = m >> 5, b = m & 31;
                float2 r1 = make_float2(acc[f][p][2] + bo.x, acc[f][p][3] + bo.y);
                *(float2*)&out[(size_t)b * NTT * NV + (size_t)tt * NV + n] = r1;
            }
        }
    }
}

// ================= final hidden state tail =================
__global__ void write_hfin(float* __restrict__ out) {
    int idx = blockIdx.x * blockDim.x + threadIdx.x;   // 65536
    int l = idx >> 14, b = (idx >> 9) & 31, j = idx & 511;
    float lo, hi; upk2(g_hb[1][l][b >> 1][j], lo, hi);
    out[(size_t)NB * NTT * NV + idx] = (b & 1) ? hi : lo;
}

extern "C" void kernel_launch(void* const* d_in, const int* in_sizes, int n_in,
                              void* d_out, int out_size)
{
    (void)in_sizes; (void)n_in; (void)out_size;
    const float* dh   = (const float*)d_in[1];
    const float* dc   = (const float*)d_in[2];
    const int*   tgt  = (const int*)  d_in[3];
    const float* emb  = (const float*)d_in[4];
    const float* Wih  = (const float*)d_in[5];
    const float* Whh  = (const float*)d_in[6];
    const float* bih  = (const float*)d_in[7];
    const float* bhh  = (const float*)d_in[8];
    const float* Wout = (const float*)d_in[9];
    const float* bout = (const float*)d_in[10];
    float* out = (float*)d_out;

    const int SMEM_LSTM = 8192 * 8 + 256 * 8 + 64;   // ~67.6KB
    const int SMEM_PROJ = 65536;
    cudaFuncSetAttribute(lstm_diag, cudaFuncAttributeMaxDynamicSharedMemorySize, SMEM_LSTM);
    cudaFuncSetAttribute(proj_mma, cudaFuncAttributeMaxDynamicSharedMemorySize, SMEM_PROJ);

    init_pair<<<128, 256>>>(dh, dc);
    init_emb<<<1632, 256>>>(emb, tgt);
    conv_w<<<8000, 256>>>(Wout);

    for (int d = 0; d < NTT + NL - 1; d++) {
        int lmin = (d > NTT - 1) ? d - (NTT - 1) : 0;
        int lmax = (d < NL - 1) ? d : NL - 1;
        int ns = lmax - lmin + 1;
        lstm_diag<<<256 * ns, 256, SMEM_LSTM>>>(d, Wih, Whh, bih, bhh);
    }

    conv_h<<<416, 256>>>();
    proj_mma<<<dim3(250, 13), 256, SMEM_PROJ>>>(bout, out);
    write_hfin<<<256, 256>>>(out);
}